// round 6
// baseline (speedup 1.0000x reference)
#include <cuda_runtime.h>

#define B_  32
#define C_  64
#define H_  128
#define W_  128
#define HW  16384
#define CR  38               // floor(0.6*64)=38, even
#define CIR 26

// fused tile (round-4 geometry): 64 px wide (16 float4) x 16 rows
#define TW4 16
#define TH  16

// Scratch (allocation-free rule: __device__ globals)
__device__ unsigned long long g_mask[B_];
__device__ float4 g_maps[B_ * HW];   // {ravg, rmax, iravg, irmax}, 8 MB

// ---------------------------------------------------------------------------
// top-k(CR) rank mask, threads 0..63 cooperate. jax top_k tiebreak: smaller
// index wins ties.
// ---------------------------------------------------------------------------
__device__ __forceinline__ unsigned long long
compute_mask(const float* __restrict__ M, int b, int t,
             float* sm, unsigned long long* smask) {
    if (t == 0) *smask = 0ull;
    if (t < C_) sm[t] = __ldg(M + b * C_ + t);
    __syncthreads();
    if (t < C_) {
        float v = sm[t];
        int rank = 0;
        #pragma unroll
        for (int j = 0; j < C_; j++) {
            float mj = sm[j];
            rank += (mj > v) || (mj == v && j < t);
        }
        if (rank < CR) atomicOr(smask, 1ull << t);
    }
    __syncthreads();
    return *smask;
}

// ---------------------------------------------------------------------------
// Kernel 1: mask + channel reductions, 4-way channel split.
// quarter = t>>6 (warp-aligned, so every warp's lanes load consecutive
// float4-groups of ONE channel -> fully coalesced). 64 groups per CTA,
// grid = 2048. Quarters 1-3 park partials in smem; quarter 0 merges.
// Masked-out entries are exact zeros in the reference -> max init to 0.
// ---------------------------------------------------------------------------
__global__ void __launch_bounds__(256) reduce_kernel(
        const float* __restrict__ x, const float* __restrict__ M) {
    __shared__ float sm[C_];
    __shared__ unsigned long long smask;
    __shared__ float4 part[3][64][4];     // 12 KB: rs, rm, is, im per group

    int t     = threadIdx.x;
    int b     = blockIdx.x >> 6;          // 64 CTAs per batch
    int slice = blockIdx.x & 63;
    int q     = t >> 6;                   // channel quarter 0..3
    int gi    = t & 63;
    int group = slice * 64 + gi;          // float4 pixel-group 0..4095

    unsigned long long mask = compute_mask(M, b, t, sm, &smask);
    if (slice == 0 && t == 0) g_mask[b] = mask;

    const float4* xb = (const float4*)(x + (size_t)b * C_ * HW)
                     + (size_t)q * 16 * (HW / 4) + group;
    unsigned long long msk = mask >> (q * 16);

    float4 rs = {0,0,0,0}, rm = {0,0,0,0};
    float4 is = {0,0,0,0}, im = {0,0,0,0};

    #pragma unroll
    for (int c = 0; c < 16; c++) {
        float4 v = __ldg(xb + c * (HW / 4));
        if ((msk >> c) & 1ull) {
            rs.x += v.x; rs.y += v.y; rs.z += v.z; rs.w += v.w;
            rm.x = fmaxf(rm.x, v.x); rm.y = fmaxf(rm.y, v.y);
            rm.z = fmaxf(rm.z, v.z); rm.w = fmaxf(rm.w, v.w);
        } else {
            is.x += v.x; is.y += v.y; is.z += v.z; is.w += v.w;
            im.x = fmaxf(im.x, v.x); im.y = fmaxf(im.y, v.y);
            im.z = fmaxf(im.z, v.z); im.w = fmaxf(im.w, v.w);
        }
    }

    if (q > 0) {
        part[q - 1][gi][0] = rs; part[q - 1][gi][1] = rm;
        part[q - 1][gi][2] = is; part[q - 1][gi][3] = im;
    }
    __syncthreads();

    if (q == 0) {
        #pragma unroll
        for (int p = 0; p < 3; p++) {
            float4 ors = part[p][gi][0], orm = part[p][gi][1];
            float4 ois = part[p][gi][2], oim = part[p][gi][3];
            rs.x += ors.x; rs.y += ors.y; rs.z += ors.z; rs.w += ors.w;
            is.x += ois.x; is.y += ois.y; is.z += ois.z; is.w += ois.w;
            rm.x = fmaxf(rm.x, orm.x); rm.y = fmaxf(rm.y, orm.y);
            rm.z = fmaxf(rm.z, orm.z); rm.w = fmaxf(rm.w, orm.w);
            im.x = fmaxf(im.x, oim.x); im.y = fmaxf(im.y, oim.y);
            im.z = fmaxf(im.z, oim.z); im.w = fmaxf(im.w, oim.w);
        }
        const float kr = 1.0f / (float)CR, ki = 1.0f / (float)CIR;
        float4* mp = g_maps + (size_t)b * HW + group * 4;
        mp[0] = make_float4(rs.x * kr, rm.x, is.x * ki, im.x);
        mp[1] = make_float4(rs.y * kr, rm.y, is.y * ki, im.y);
        mp[2] = make_float4(rs.z * kr, rm.z, is.z * ki, im.z);
        mp[3] = make_float4(rs.w * kr, rm.w, is.w * ki, im.w);
    }
}

// ---------------------------------------------------------------------------
// Kernel 2: fused conv(7x7, pad 3) + BN + relu + sigmoid + combine.
// Round-4 structure (conv from global register segments, 46 regs) but the
// channel loop is split across 2 CTAs per tile (32 channels each), doubling
// the grid to 1024 for occupancy. Conv recomputed per CTA (L2-cheap).
// ---------------------------------------------------------------------------
__global__ void __launch_bounds__(256) fused_kernel(
        const float* __restrict__ x,
        float* __restrict__ out,
        const float* __restrict__ cw,
        const float* __restrict__ gamma,
        const float* __restrict__ beta,
        const float* __restrict__ mean,
        const float* __restrict__ var) {
    __shared__ float sw[98];

    int t = threadIdx.x;
    int tile = blockIdx.x >> 1;             // 0..511
    int half = blockIdx.x & 1;              // channel half
    int b  = tile >> 4;                     // 16 tiles per batch
    int ti = tile & 15;
    int h0 = (ti >> 1) * TH;                // 8 tile-rows
    int w0 = (ti & 1) * (TW4 * 4);          // 2 tile-cols (0 or 64)

    if (t < 98) sw[t] = __ldg(cw + t);
    __syncthreads();

    int ty = t >> 4;                        // 0..15
    int tx = t & 15;                        // 0..15
    int h  = h0 + ty;
    int wb = w0 + tx * 4;

    const float4* mb = g_maps + (size_t)b * HW;

    float y1[4] = {0,0,0,0}, y2[4] = {0,0,0,0};

    #pragma unroll
    for (int kh = 0; kh < 7; kh++) {
        int gh = h + kh - 3;
        float4 seg[10];
        #pragma unroll
        for (int s = 0; s < 10; s++) {
            int gw = wb + s - 3;
            float4 v = {0,0,0,0};
            if (gh >= 0 && gh < H_ && gw >= 0 && gw < W_)
                v = __ldg(mb + gh * W_ + gw);
            seg[s] = v;
        }
        #pragma unroll
        for (int kw = 0; kw < 7; kw++) {
            float w0c = sw[kh * 7 + kw];
            float w1c = sw[49 + kh * 7 + kw];
            #pragma unroll
            for (int j = 0; j < 4; j++) {
                float4 m = seg[j + kw];
                y1[j] = fmaf(m.x, w0c, fmaf(m.y, w1c, y1[j]));
                y2[j] = fmaf(m.z, w0c, fmaf(m.w, w1c, y2[j]));
            }
        }
    }

    float scale = rsqrtf(__ldg(var) + 1e-5f) * __ldg(gamma);
    float bias  = __ldg(beta) - __ldg(mean) * scale;
    float a1[4], a2[4];
    #pragma unroll
    for (int j = 0; j < 4; j++) {
        float v1 = fmaxf(fmaf(y1[j], scale, bias), 0.f);
        float v2 = fmaxf(fmaf(y2[j], scale, bias), 0.f);
        a1[j] = 1.0f / (1.0f + expf(-v1));
        a2[j] = 1.0f / (1.0f + expf(-v2));
    }

    // channel loop: 32 channels for this CTA's half
    unsigned long long mask = g_mask[b] >> (half * 32);
    size_t base4 = ((size_t)b * C_ * HW + h * W_ + wb) >> 2;
    const float4* xp = (const float4*)x + base4 + (size_t)half * 32 * (HW / 4);
    float4*       op = (float4*)out     + base4 + (size_t)half * 32 * (HW / 4);

    #pragma unroll 8
    for (int c = 0; c < 32; c++) {
        bool rel = (mask >> c) & 1ull;
        float4 v = __ldg(xp + c * (HW / 4));
        float4 r;
        r.x = v.x * (rel ? a1[0] : a2[0]);
        r.y = v.y * (rel ? a1[1] : a2[1]);
        r.z = v.z * (rel ? a1[2] : a2[2]);
        r.w = v.w * (rel ? a1[3] : a2[3]);
        op[c * (HW / 4)] = r;
    }
}

// ---------------------------------------------------------------------------
extern "C" void kernel_launch(void* const* d_in, const int* in_sizes, int n_in,
                              void* d_out, int out_size) {
    const float* x     = (const float*)d_in[0];
    const float* M     = (const float*)d_in[1];
    const float* cw    = (const float*)d_in[2];
    const float* gamma = (const float*)d_in[3];
    const float* beta  = (const float*)d_in[4];
    const float* mean  = (const float*)d_in[5];
    const float* var   = (const float*)d_in[6];
    float* out = (float*)d_out;

    reduce_kernel<<<B_ * 64, 256>>>(x, M);                      // 2048 CTAs
    fused_kernel <<<B_ * 32, 256>>>(x, out, cw, gamma, beta, mean, var); // 1024
}

// round 8
// speedup vs baseline: 1.2414x; 1.2414x over previous
#include <cuda_runtime.h>

#define B_  32
#define C_  64
#define H_  128
#define W_  128
#define HW  16384
#define CR  38               // floor(0.6*64)=38, even
#define CIR 26

// conv tile: 64 wide x 4 high, 256 threads = 1 px/thread
#define CTW 64
#define CTH 4
#define HALO_W 70
#define HALO_H 10

// Scratch (allocation-free rule: __device__ globals)
__device__ unsigned long long g_mask[B_];
__device__ float4 g_maps[B_ * HW];   // {ravg, rmax, iravg, irmax}, 8 MB
__device__ float  g_A1  [B_ * HW];   // 2 MB
__device__ float  g_A2  [B_ * HW];   // 2 MB

// ---------------------------------------------------------------------------
// top-k(CR) rank mask for batch b; all 64 threads of the CTA cooperate.
// jax top_k tiebreak: smaller index wins ties.
// ---------------------------------------------------------------------------
__device__ __forceinline__ unsigned long long
compute_mask64(const float* __restrict__ M, int b, int t,
               float* sm, unsigned long long* smask) {
    if (t == 0) *smask = 0ull;
    sm[t] = __ldg(M + b * C_ + t);
    __syncthreads();
    float v = sm[t];
    int rank = 0;
    #pragma unroll
    for (int j = 0; j < C_; j++) {
        float mj = sm[j];
        rank += (mj > v) || (mj == v && j < t);
    }
    if (rank < CR) atomicOr(smask, 1ull << t);
    __syncthreads();
    return *smask;
}

// ---------------------------------------------------------------------------
// Kernel 1: mask + channel reductions. 2048 CTAs x 64 threads (13.8 CTAs/SM,
// near-perfect SM balance). Thread = 1 float4 pixel-group, 64 channel loads.
// Masked-out entries are exact zeros in the reference -> max init to 0.
// ---------------------------------------------------------------------------
__global__ void __launch_bounds__(64) reduce_kernel(
        const float* __restrict__ x, const float* __restrict__ M) {
    __shared__ float sm[C_];
    __shared__ unsigned long long smask;

    int t     = threadIdx.x;                // 0..63
    int b     = blockIdx.x >> 6;            // 64 CTAs per batch
    int slice = blockIdx.x & 63;
    int group = slice * 64 + t;             // float4 pixel-group 0..4095

    unsigned long long mask = compute_mask64(M, b, t, sm, &smask);
    if (slice == 0 && t == 0) g_mask[b] = mask;

    const float4* xb = (const float4*)(x + (size_t)b * C_ * HW) + group;

    float4 rs = {0,0,0,0}, rm = {0,0,0,0};
    float4 is = {0,0,0,0}, im = {0,0,0,0};

    #pragma unroll
    for (int c = 0; c < C_; c++) {
        float4 v = __ldg(xb + c * (HW / 4));
        if ((mask >> c) & 1ull) {
            rs.x += v.x; rs.y += v.y; rs.z += v.z; rs.w += v.w;
            rm.x = fmaxf(rm.x, v.x); rm.y = fmaxf(rm.y, v.y);
            rm.z = fmaxf(rm.z, v.z); rm.w = fmaxf(rm.w, v.w);
        } else {
            is.x += v.x; is.y += v.y; is.z += v.z; is.w += v.w;
            im.x = fmaxf(im.x, v.x); im.y = fmaxf(im.y, v.y);
            im.z = fmaxf(im.z, v.z); im.w = fmaxf(im.w, v.w);
        }
    }

    const float kr = 1.0f / (float)CR, ki = 1.0f / (float)CIR;
    float4* mp = g_maps + (size_t)b * HW + group * 4;
    mp[0] = make_float4(rs.x * kr, rm.x, is.x * ki, im.x);
    mp[1] = make_float4(rs.y * kr, rm.y, is.y * ki, im.y);
    mp[2] = make_float4(rs.z * kr, rm.z, is.z * ki, im.z);
    mp[3] = make_float4(rs.w * kr, rm.w, is.w * ki, im.w);
}

// ---------------------------------------------------------------------------
// Kernel 2: 7x7 conv (2ch->1, zero-pad 3) + BN + relu + sigmoid -> A1, A2.
// CTA = 64x4 px tile, halo in smem (70x10 float4 = 11.2 KB), 1 px/thread.
// Inputs (g_maps) and outputs (g_A1/g_A2) are L2-resident.
// ---------------------------------------------------------------------------
__global__ void __launch_bounds__(256) conv_kernel(
        const float* __restrict__ cw,
        const float* __restrict__ gamma,
        const float* __restrict__ beta,
        const float* __restrict__ mean,
        const float* __restrict__ var) {
    __shared__ float4 smaps[HALO_H][HALO_W];    // 11.2 KB
    __shared__ float sw[98];

    int t  = threadIdx.x;
    int b  = blockIdx.x >> 6;               // 64 tiles per batch
    int ti = blockIdx.x & 63;
    int h0 = (ti >> 1) * CTH;               // 32 tile-rows
    int w0 = (ti & 1) * CTW;                // 2 tile-cols

    if (t < 98) sw[t] = __ldg(cw + t);

    const float4* mb = g_maps + (size_t)b * HW;
    for (int i = t; i < HALO_H * HALO_W; i += 256) {
        int r  = i / HALO_W;
        int cx = i - r * HALO_W;
        int gh = h0 + r - 3;
        int gw = w0 + cx - 3;
        float4 v = {0,0,0,0};
        if (gh >= 0 && gh < H_ && gw >= 0 && gw < W_)
            v = __ldg(mb + gh * W_ + gw);
        smaps[r][cx] = v;
    }
    __syncthreads();

    int hh = t >> 6;                        // 0..3
    int w  = t & 63;                        // 0..63

    float y1 = 0.f, y2 = 0.f;
    #pragma unroll
    for (int kh = 0; kh < 7; kh++) {
        #pragma unroll
        for (int kw = 0; kw < 7; kw++) {
            float w0c = sw[kh * 7 + kw];
            float w1c = sw[49 + kh * 7 + kw];
            float4 m = smaps[hh + kh][w + kw];
            y1 = fmaf(m.x, w0c, fmaf(m.y, w1c, y1));
            y2 = fmaf(m.z, w0c, fmaf(m.w, w1c, y2));
        }
    }

    float scale = rsqrtf(__ldg(var) + 1e-5f) * __ldg(gamma);
    float bias  = __ldg(beta) - __ldg(mean) * scale;
    y1 = fmaxf(fmaf(y1, scale, bias), 0.f);
    y2 = fmaxf(fmaf(y2, scale, bias), 0.f);

    int p = b * HW + (h0 + hh) * W_ + (w0 + w);   // FIXED: include w0
    g_A1[p] = 1.0f / (1.0f + expf(-y1));
    g_A2[p] = 1.0f / (1.0f + expf(-y2));
}

// ---------------------------------------------------------------------------
// Kernel 3: out = x * (relevant-channel ? A_S1 : A_S2), float4-vectorized.
// (Round-1 kernel verbatim: measured 42.6 us @ 6.1 TB/s.)
// ---------------------------------------------------------------------------
__global__ void combine_kernel(const float* __restrict__ x,
                               float* __restrict__ out) {
    size_t i = (size_t)blockIdx.x * blockDim.x + threadIdx.x;  // float4 index
    size_t e = i << 2;                                         // element index
    int b    = (int)(e >> 20);          // C_*HW = 2^20
    int c    = (int)((e >> 14) & 63);
    int pix4 = (int)((e & (HW - 1)) >> 2);

    const float4* x4 = (const float4*)x;
    float4 v = x4[i];

    bool rel = (g_mask[b] >> c) & 1ull;
    const float4* A4 = (const float4*)(rel ? g_A1 : g_A2);
    float4 a = __ldg(A4 + ((size_t)b * HW >> 2) + pix4);

    float4 r;
    r.x = v.x * a.x;
    r.y = v.y * a.y;
    r.z = v.z * a.z;
    r.w = v.w * a.w;
    ((float4*)out)[i] = r;
}

// ---------------------------------------------------------------------------
extern "C" void kernel_launch(void* const* d_in, const int* in_sizes, int n_in,
                              void* d_out, int out_size) {
    const float* x     = (const float*)d_in[0];
    const float* M     = (const float*)d_in[1];
    const float* cw    = (const float*)d_in[2];
    const float* gamma = (const float*)d_in[3];
    const float* beta  = (const float*)d_in[4];
    const float* mean  = (const float*)d_in[5];
    const float* var   = (const float*)d_in[6];
    float* out = (float*)d_out;

    reduce_kernel<<<B_ * 64, 64>>>(x, M);                // 2048 CTAs x 64
    conv_kernel  <<<B_ * 64, 256>>>(cw, gamma, beta, mean, var);  // 2048 CTAs

    const int NV4 = (B_ * C_ * HW) / 4;                  // 8388608
    combine_kernel<<<NV4 / 256, 256>>>(x, out);          // 32768 CTAs
}

// round 9
// speedup vs baseline: 1.3028x; 1.0494x over previous
#include <cuda_runtime.h>

#define B_  32
#define C_  64
#define H_  128
#define W_  128
#define HW  16384
#define CR  38               // floor(0.6*64)=38, even
#define CIR 26

// conv tile: 64 wide x 16 high, 256 threads = 64 tx x 4 ty, 4 rows/thread
#define CTW 64
#define CTH 16
#define HALO_W 70            // 64+6
#define HALO_H 22            // 16+6

// Scratch (allocation-free rule: __device__ globals)
__device__ unsigned long long g_mask[B_];
__device__ float4 g_maps[B_ * HW];   // {ravg, rmax, iravg, irmax}, 8 MB
__device__ float  g_A1  [B_ * HW];   // 2 MB
__device__ float  g_A2  [B_ * HW];   // 2 MB

// ---------------------------------------------------------------------------
// top-k(CR) rank mask for batch b; 64 threads cooperate.
// jax top_k tiebreak: smaller index wins ties.
// ---------------------------------------------------------------------------
__device__ __forceinline__ unsigned long long
compute_mask64(const float* __restrict__ M, int b, int t,
               float* sm, unsigned long long* smask) {
    if (t == 0) *smask = 0ull;
    sm[t] = __ldg(M + b * C_ + t);
    __syncthreads();
    float v = sm[t];
    int rank = 0;
    #pragma unroll
    for (int j = 0; j < C_; j++) {
        float mj = sm[j];
        rank += (mj > v) || (mj == v && j < t);
    }
    if (rank < CR) atomicOr(smask, 1ull << t);
    __syncthreads();
    return *smask;
}

// ---------------------------------------------------------------------------
// Kernel 1: mask + channel reductions, half-warp channel split.
// Lanes 0-15 reduce channels 0-31, lanes 16-31 reduce channels 32-63 for the
// SAME 16 float4 pixel-groups; merged with shfl_xor(16). 4096 CTAs x 64 thr
// -> 55 warps/SM. Masked-out entries are exact zeros -> max init 0.
// ---------------------------------------------------------------------------
__global__ void __launch_bounds__(64) reduce_kernel(
        const float* __restrict__ x, const float* __restrict__ M) {
    __shared__ float sm[C_];
    __shared__ unsigned long long smask;

    int t     = threadIdx.x;                // 0..63
    int b     = blockIdx.x >> 7;            // 128 CTAs per batch
    int slice = blockIdx.x & 127;

    unsigned long long mask = compute_mask64(M, b, t, sm, &smask);
    if (slice == 0 && t == 0) g_mask[b] = mask;

    int warp = t >> 5;
    int lane = t & 31;
    int half = lane >> 4;                   // 0: ch 0-31, 1: ch 32-63
    int li   = lane & 15;
    int group = slice * 32 + warp * 16 + li;   // float4 pixel-group 0..4095

    const float4* xb = (const float4*)(x + (size_t)b * C_ * HW)
                     + (size_t)half * 32 * (HW / 4) + group;
    unsigned long long msk = mask >> (half * 32);

    float4 rs = {0,0,0,0}, rm = {0,0,0,0};
    float4 is = {0,0,0,0}, im = {0,0,0,0};

    #pragma unroll
    for (int c = 0; c < 32; c++) {
        float4 v = __ldg(xb + c * (HW / 4));
        if ((msk >> c) & 1ull) {
            rs.x += v.x; rs.y += v.y; rs.z += v.z; rs.w += v.w;
            rm.x = fmaxf(rm.x, v.x); rm.y = fmaxf(rm.y, v.y);
            rm.z = fmaxf(rm.z, v.z); rm.w = fmaxf(rm.w, v.w);
        } else {
            is.x += v.x; is.y += v.y; is.z += v.z; is.w += v.w;
            im.x = fmaxf(im.x, v.x); im.y = fmaxf(im.y, v.y);
            im.z = fmaxf(im.z, v.z); im.w = fmaxf(im.w, v.w);
        }
    }

    // merge the two channel halves across the half-warp boundary
    const unsigned FULL = 0xffffffffu;
    rs.x += __shfl_xor_sync(FULL, rs.x, 16); rs.y += __shfl_xor_sync(FULL, rs.y, 16);
    rs.z += __shfl_xor_sync(FULL, rs.z, 16); rs.w += __shfl_xor_sync(FULL, rs.w, 16);
    is.x += __shfl_xor_sync(FULL, is.x, 16); is.y += __shfl_xor_sync(FULL, is.y, 16);
    is.z += __shfl_xor_sync(FULL, is.z, 16); is.w += __shfl_xor_sync(FULL, is.w, 16);
    rm.x = fmaxf(rm.x, __shfl_xor_sync(FULL, rm.x, 16));
    rm.y = fmaxf(rm.y, __shfl_xor_sync(FULL, rm.y, 16));
    rm.z = fmaxf(rm.z, __shfl_xor_sync(FULL, rm.z, 16));
    rm.w = fmaxf(rm.w, __shfl_xor_sync(FULL, rm.w, 16));
    im.x = fmaxf(im.x, __shfl_xor_sync(FULL, im.x, 16));
    im.y = fmaxf(im.y, __shfl_xor_sync(FULL, im.y, 16));
    im.z = fmaxf(im.z, __shfl_xor_sync(FULL, im.z, 16));
    im.w = fmaxf(im.w, __shfl_xor_sync(FULL, im.w, 16));

    if (half == 0) {
        const float kr = 1.0f / (float)CR, ki = 1.0f / (float)CIR;
        float4* mp = g_maps + (size_t)b * HW + group * 4;
        mp[0] = make_float4(rs.x * kr, rm.x, is.x * ki, im.x);
        mp[1] = make_float4(rs.y * kr, rm.y, is.y * ki, im.y);
        mp[2] = make_float4(rs.z * kr, rm.z, is.z * ki, im.z);
        mp[3] = make_float4(rs.w * kr, rm.w, is.w * ki, im.w);
    }
}

// ---------------------------------------------------------------------------
// Kernel 2: 7x7 conv (2ch->1, zero-pad 3) + BN + relu + sigmoid -> A1, A2.
// CTA = 64x16 tile. Thread = col tx, rows ty*4..ty*4+3. Per kw: one 10-tall
// vertical register segment (conflict-free contiguous LDS.128 across lanes),
// reused over all 7 kh and the 4 output rows -> 70 LDS.128 per 4 pixels.
// ---------------------------------------------------------------------------
__global__ void __launch_bounds__(256) conv_kernel(
        const float* __restrict__ cw,
        const float* __restrict__ gamma,
        const float* __restrict__ beta,
        const float* __restrict__ mean,
        const float* __restrict__ var) {
    __shared__ float4 smaps[HALO_H][HALO_W];    // 24.6 KB
    __shared__ float sw[98];

    int t  = threadIdx.x;
    int b  = blockIdx.x >> 4;               // 16 tiles per batch
    int ti = blockIdx.x & 15;
    int h0 = (ti >> 1) * CTH;               // 8 tile-rows
    int w0 = (ti & 1) * CTW;                // 2 tile-cols

    if (t < 98) sw[t] = __ldg(cw + t);

    const float4* mb = g_maps + (size_t)b * HW;
    for (int i = t; i < HALO_H * HALO_W; i += 256) {
        int r  = i / HALO_W;
        int cx = i - r * HALO_W;
        int gh = h0 + r - 3;
        int gw = w0 + cx - 3;
        float4 v = {0,0,0,0};
        if (gh >= 0 && gh < H_ && gw >= 0 && gw < W_)
            v = __ldg(mb + gh * W_ + gw);
        smaps[r][cx] = v;
    }
    __syncthreads();

    int tx = t & 63;                        // 0..63  (lane-consecutive cols)
    int ty = t >> 6;                        // 0..3   (4-row group)
    int r0 = ty * 4;                        // first local output row

    float y1[4] = {0,0,0,0}, y2[4] = {0,0,0,0};

    #pragma unroll
    for (int kw = 0; kw < 7; kw++) {
        float4 seg[10];
        #pragma unroll
        for (int s = 0; s < 10; s++)
            seg[s] = smaps[r0 + s][tx + kw];
        #pragma unroll
        for (int kh = 0; kh < 7; kh++) {
            float w0c = sw[kh * 7 + kw];
            float w1c = sw[49 + kh * 7 + kw];
            #pragma unroll
            for (int j = 0; j < 4; j++) {
                float4 m = seg[j + kh];
                y1[j] = fmaf(m.x, w0c, fmaf(m.y, w1c, y1[j]));
                y2[j] = fmaf(m.z, w0c, fmaf(m.w, w1c, y2[j]));
            }
        }
    }

    float scale = rsqrtf(__ldg(var) + 1e-5f) * __ldg(gamma);
    float bias  = __ldg(beta) - __ldg(mean) * scale;

    #pragma unroll
    for (int j = 0; j < 4; j++) {
        float v1 = fmaxf(fmaf(y1[j], scale, bias), 0.f);
        float v2 = fmaxf(fmaf(y2[j], scale, bias), 0.f);
        int p = b * HW + (h0 + r0 + j) * W_ + (w0 + tx);
        g_A1[p] = 1.0f / (1.0f + expf(-v1));
        g_A2[p] = 1.0f / (1.0f + expf(-v2));
    }
}

// ---------------------------------------------------------------------------
// Kernel 3: out = x * (relevant-channel ? A_S1 : A_S2), float4-vectorized.
// Streaming hints: x/out evict-first (no reuse); A-maps default (L2-hit).
// ---------------------------------------------------------------------------
__global__ void combine_kernel(const float* __restrict__ x,
                               float* __restrict__ out) {
    size_t i = (size_t)blockIdx.x * blockDim.x + threadIdx.x;  // float4 index
    size_t e = i << 2;                                         // element index
    int b    = (int)(e >> 20);          // C_*HW = 2^20
    int c    = (int)((e >> 14) & 63);
    int pix4 = (int)((e & (HW - 1)) >> 2);

    float4 v = __ldcs((const float4*)x + i);

    bool rel = (g_mask[b] >> c) & 1ull;
    const float4* A4 = (const float4*)(rel ? g_A1 : g_A2);
    float4 a = __ldg(A4 + ((size_t)b * HW >> 2) + pix4);

    float4 r;
    r.x = v.x * a.x;
    r.y = v.y * a.y;
    r.z = v.z * a.z;
    r.w = v.w * a.w;
    __stcs((float4*)out + i, r);
}

// ---------------------------------------------------------------------------
extern "C" void kernel_launch(void* const* d_in, const int* in_sizes, int n_in,
                              void* d_out, int out_size) {
    const float* x     = (const float*)d_in[0];
    const float* M     = (const float*)d_in[1];
    const float* cw    = (const float*)d_in[2];
    const float* gamma = (const float*)d_in[3];
    const float* beta  = (const float*)d_in[4];
    const float* mean  = (const float*)d_in[5];
    const float* var   = (const float*)d_in[6];
    float* out = (float*)d_out;

    reduce_kernel<<<B_ * 128, 64>>>(x, M);                        // 4096 CTAs
    conv_kernel  <<<B_ * 16, 256>>>(cw, gamma, beta, mean, var);  // 512 CTAs

    const int NV4 = (B_ * C_ * HW) / 4;                  // 8388608
    combine_kernel<<<NV4 / 256, 256>>>(x, out);          // 32768 CTAs
}

// round 10
// speedup vs baseline: 1.4000x; 1.0746x over previous
#include <cuda_runtime.h>

#define B_  32
#define C_  64
#define H_  128
#define W_  128
#define HW  16384
#define CR  38               // floor(0.6*64)=38, even
#define CIR 26

// conv tile: 64 wide x 16 high, 256 threads = 64 tx x 4 ty, 4 rows/thread
#define CTW 64
#define CTH 16
#define HALO_W 70            // 64+6
#define HALO_H 22            // 16+6

// Scratch (allocation-free rule: __device__ globals)
__device__ unsigned long long g_mask[B_];
__device__ float4 g_maps[B_ * HW];   // {ravg, rmax, iravg, irmax}, 8 MB
__device__ float  g_A1  [B_ * HW];   // 2 MB
__device__ float  g_A2  [B_ * HW];   // 2 MB

// ---------------------------------------------------------------------------
// top-k(CR) rank mask for batch b; 64 threads cooperate.
// jax top_k tiebreak: smaller index wins ties.
// ---------------------------------------------------------------------------
__device__ __forceinline__ unsigned long long
compute_mask64(const float* __restrict__ M, int b, int t,
               float* sm, unsigned long long* smask) {
    if (t == 0) *smask = 0ull;
    sm[t] = __ldg(M + b * C_ + t);
    __syncthreads();
    float v = sm[t];
    int rank = 0;
    #pragma unroll
    for (int j = 0; j < C_; j++) {
        float mj = sm[j];
        rank += (mj > v) || (mj == v && j < t);
    }
    if (rank < CR) atomicOr(smask, 1ull << t);
    __syncthreads();
    return *smask;
}

// ---------------------------------------------------------------------------
// Kernel 1: mask + channel reductions. 2048 CTAs x 64 threads, thread = one
// float4 pixel-group x 64 channels (warp-wide 512 B contiguous per channel).
// Explicit 8-deep load batches to maximize in-flight LDG.128 (MLP).
// Masked-out entries are exact zeros in the reference -> max init to 0.
// ---------------------------------------------------------------------------
__global__ void __launch_bounds__(64) reduce_kernel(
        const float* __restrict__ x, const float* __restrict__ M) {
    __shared__ float sm[C_];
    __shared__ unsigned long long smask;

    int t     = threadIdx.x;                // 0..63
    int b     = blockIdx.x >> 6;            // 64 CTAs per batch
    int slice = blockIdx.x & 63;
    int group = slice * 64 + t;             // float4 pixel-group 0..4095

    unsigned long long mask = compute_mask64(M, b, t, sm, &smask);
    if (slice == 0 && t == 0) g_mask[b] = mask;

    const float4* xb = (const float4*)(x + (size_t)b * C_ * HW) + group;

    float4 rs = {0,0,0,0}, rm = {0,0,0,0};
    float4 is = {0,0,0,0}, im = {0,0,0,0};

    #pragma unroll
    for (int cb = 0; cb < C_; cb += 8) {
        float4 v[8];
        #pragma unroll
        for (int j = 0; j < 8; j++)
            v[j] = __ldg(xb + (cb + j) * (HW / 4));
        #pragma unroll
        for (int j = 0; j < 8; j++) {
            if ((mask >> (cb + j)) & 1ull) {
                rs.x += v[j].x; rs.y += v[j].y; rs.z += v[j].z; rs.w += v[j].w;
                rm.x = fmaxf(rm.x, v[j].x); rm.y = fmaxf(rm.y, v[j].y);
                rm.z = fmaxf(rm.z, v[j].z); rm.w = fmaxf(rm.w, v[j].w);
            } else {
                is.x += v[j].x; is.y += v[j].y; is.z += v[j].z; is.w += v[j].w;
                im.x = fmaxf(im.x, v[j].x); im.y = fmaxf(im.y, v[j].y);
                im.z = fmaxf(im.z, v[j].z); im.w = fmaxf(im.w, v[j].w);
            }
        }
    }

    const float kr = 1.0f / (float)CR, ki = 1.0f / (float)CIR;
    float4* mp = g_maps + (size_t)b * HW + group * 4;
    mp[0] = make_float4(rs.x * kr, rm.x, is.x * ki, im.x);
    mp[1] = make_float4(rs.y * kr, rm.y, is.y * ki, im.y);
    mp[2] = make_float4(rs.z * kr, rm.z, is.z * ki, im.z);
    mp[3] = make_float4(rs.w * kr, rm.w, is.w * ki, im.w);
}

// ---------------------------------------------------------------------------
// Kernel 2: 7x7 conv (2ch->1, zero-pad 3) + BN + relu + sigmoid -> A1, A2.
// CTA = 64x16 tile. Thread = col tx, rows ty*4..ty*4+3. Per kw: one 10-tall
// vertical register segment (conflict-free contiguous LDS.128 across lanes),
// reused over all 7 kh and 4 output rows -> 70 LDS.128 per 4 pixels.
// ---------------------------------------------------------------------------
__global__ void __launch_bounds__(256) conv_kernel(
        const float* __restrict__ cw,
        const float* __restrict__ gamma,
        const float* __restrict__ beta,
        const float* __restrict__ mean,
        const float* __restrict__ var) {
    __shared__ float4 smaps[HALO_H][HALO_W];    // 24.6 KB
    __shared__ float sw[98];

    int t  = threadIdx.x;
    int b  = blockIdx.x >> 4;               // 16 tiles per batch
    int ti = blockIdx.x & 15;
    int h0 = (ti >> 1) * CTH;               // 8 tile-rows
    int w0 = (ti & 1) * CTW;                // 2 tile-cols

    if (t < 98) sw[t] = __ldg(cw + t);

    const float4* mb = g_maps + (size_t)b * HW;
    for (int i = t; i < HALO_H * HALO_W; i += 256) {
        int r  = i / HALO_W;
        int cx = i - r * HALO_W;
        int gh = h0 + r - 3;
        int gw = w0 + cx - 3;
        float4 v = {0,0,0,0};
        if (gh >= 0 && gh < H_ && gw >= 0 && gw < W_)
            v = __ldg(mb + gh * W_ + gw);
        smaps[r][cx] = v;
    }
    __syncthreads();

    int tx = t & 63;                        // 0..63  (lane-consecutive cols)
    int ty = t >> 6;                        // 0..3   (4-row group)
    int r0 = ty * 4;                        // first local output row

    float y1[4] = {0,0,0,0}, y2[4] = {0,0,0,0};

    #pragma unroll
    for (int kw = 0; kw < 7; kw++) {
        float4 seg[10];
        #pragma unroll
        for (int s = 0; s < 10; s++)
            seg[s] = smaps[r0 + s][tx + kw];
        #pragma unroll
        for (int kh = 0; kh < 7; kh++) {
            float w0c = sw[kh * 7 + kw];
            float w1c = sw[49 + kh * 7 + kw];
            #pragma unroll
            for (int j = 0; j < 4; j++) {
                float4 m = seg[j + kh];
                y1[j] = fmaf(m.x, w0c, fmaf(m.y, w1c, y1[j]));
                y2[j] = fmaf(m.z, w0c, fmaf(m.w, w1c, y2[j]));
            }
        }
    }

    float scale = rsqrtf(__ldg(var) + 1e-5f) * __ldg(gamma);
    float bias  = __ldg(beta) - __ldg(mean) * scale;

    #pragma unroll
    for (int j = 0; j < 4; j++) {
        float v1 = fmaxf(fmaf(y1[j], scale, bias), 0.f);
        float v2 = fmaxf(fmaf(y2[j], scale, bias), 0.f);
        int p = b * HW + (h0 + r0 + j) * W_ + (w0 + tx);
        g_A1[p] = 1.0f / (1.0f + expf(-v1));
        g_A2[p] = 1.0f / (1.0f + expf(-v2));
    }
}

// ---------------------------------------------------------------------------
// Kernel 3: out = x * (relevant-channel ? A_S1 : A_S2), float4-vectorized.
// Streaming hints: x/out evict-first (no reuse); A-maps default (L2-hit).
// ---------------------------------------------------------------------------
__global__ void combine_kernel(const float* __restrict__ x,
                               float* __restrict__ out) {
    size_t i = (size_t)blockIdx.x * blockDim.x + threadIdx.x;  // float4 index
    size_t e = i << 2;                                         // element index
    int b    = (int)(e >> 20);          // C_*HW = 2^20
    int c    = (int)((e >> 14) & 63);
    int pix4 = (int)((e & (HW - 1)) >> 2);

    float4 v = __ldcs((const float4*)x + i);

    bool rel = (g_mask[b] >> c) & 1ull;
    const float4* A4 = (const float4*)(rel ? g_A1 : g_A2);
    float4 a = __ldg(A4 + ((size_t)b * HW >> 2) + pix4);

    float4 r;
    r.x = v.x * a.x;
    r.y = v.y * a.y;
    r.z = v.z * a.z;
    r.w = v.w * a.w;
    __stcs((float4*)out + i, r);
}

// ---------------------------------------------------------------------------
extern "C" void kernel_launch(void* const* d_in, const int* in_sizes, int n_in,
                              void* d_out, int out_size) {
    const float* x     = (const float*)d_in[0];
    const float* M     = (const float*)d_in[1];
    const float* cw    = (const float*)d_in[2];
    const float* gamma = (const float*)d_in[3];
    const float* beta  = (const float*)d_in[4];
    const float* mean  = (const float*)d_in[5];
    const float* var   = (const float*)d_in[6];
    float* out = (float*)d_out;

    reduce_kernel<<<B_ * 64, 64>>>(x, M);                         // 2048 CTAs
    conv_kernel  <<<B_ * 16, 256>>>(cw, gamma, beta, mean, var);  // 512 CTAs

    const int NV4 = (B_ * C_ * HW) / 4;                  // 8388608
    combine_kernel<<<NV4 / 256, 256>>>(x, out);          // 32768 CTAs
}